// round 1
// baseline (speedup 1.0000x reference)
#include <cuda_runtime.h>
#include <cstdint>
#include <cstddef>

#define B_  64
#define S_  512
#define E_  1024
#define H_  1024
#define NG  4096            // 4 gates * H
#define NCTA 128

typedef unsigned long long ull;

// ---------------- device scratch (static: no allocations allowed) ----------
__device__ float g_xg[(size_t)S_ * B_ * NG];   // [t][b][n]  512 MB
__device__ float g_h[2][B_ * H_];              // double-buffered hidden state [b][k]
__device__ unsigned g_bar_count = 0;
__device__ unsigned g_bar_gen   = 0;

// ---------------- packed fp32x2 helpers (full-rate fp32 on sm_103a) --------
__device__ __forceinline__ void fma2(ull& d, ull a, ull b) {
    asm("fma.rn.f32x2 %0, %1, %2, %0;" : "+l"(d) : "l"(a), "l"(b));
}
__device__ __forceinline__ float unpk_sum(ull v) {
    float x, y;
    asm("mov.b64 {%0,%1}, %2;" : "=f"(x), "=f"(y) : "l"(v));
    return x + y;
}

__device__ __forceinline__ float sigm(float z) { return 1.f / (1.f + expf(-z)); }

// ===========================================================================
// Phase 1: Xg[t][b][n] = x[b][t][:] . Wx[n][:]   (x-part of all 4 gate GEMMs)
// M = B*S = 32768 (row m = b*512+t), N = 4096, K = 1024
// CTA tile 128(M) x 64(N), packed-k fp32x2 accumulation.
// ===========================================================================
#define P1_TM 128
#define P1_TN 64
#define P1_KC 32

__global__ void __launch_bounds__(256, 2) lstm_xgemm(
    const float* __restrict__ x,
    const float* __restrict__ Wf, const float* __restrict__ Wi,
    const float* __restrict__ Wc, const float* __restrict__ Wo)
{
    __shared__ float xs[P1_TM][P1_KC + 4];
    __shared__ float ws[P1_TN][P1_KC + 4];

    const int tid = threadIdx.x;
    const int m0  = blockIdx.y * P1_TM;
    const int n0  = blockIdx.x * P1_TN;            // combined gate-col index
    const int gate = n0 >> 10;
    const int hc0  = n0 & (H_ - 1);
    const float* W = (gate == 0) ? Wf : (gate == 1) ? Wi : (gate == 2) ? Wc : Wo;

    const int lane = tid & 31, warp = tid >> 5;
    const int wm = warp & 3, wn = warp >> 2;       // 4 m-warps x 2 n-warps
    const int ml = lane & 7, nl = lane >> 3;       // 8 m-lanes x 4 n-lanes

    ull acc[4][8];
#pragma unroll
    for (int i = 0; i < 4; i++)
#pragma unroll
        for (int j = 0; j < 8; j++) acc[i][j] = 0ull;

    for (int k0 = 0; k0 < E_; k0 += P1_KC) {
        // stage x tile (128x32) + W tile (64x32): 1536 float4 / 256 threads
#pragma unroll
        for (int j = 0; j < 6; j++) {
            int f = tid + j * 256;
            if (f < 1024) {
                int r = f >> 3, c = f & 7;
                float4 v = *(const float4*)(x + (size_t)(m0 + r) * E_ + k0 + c * 4);
                *(float4*)&xs[r][c * 4] = v;
            } else {
                int f2 = f - 1024;
                int r = f2 >> 3, c = f2 & 7;
                float4 v = *(const float4*)(W + (size_t)(hc0 + r) * 2048 + k0 + c * 4);
                *(float4*)&ws[r][c * 4] = v;
            }
        }
        __syncthreads();
#pragma unroll
        for (int kk = 0; kk < P1_KC; kk += 4) {
            ulonglong2 xf[4];
#pragma unroll
            for (int mj = 0; mj < 4; mj++)
                xf[mj] = *(const ulonglong2*)&xs[wm * 32 + mj * 8 + ml][kk];
#pragma unroll
            for (int nj = 0; nj < 8; nj++) {
                ulonglong2 wv = *(const ulonglong2*)&ws[wn * 32 + nj * 4 + nl][kk];
#pragma unroll
                for (int mj = 0; mj < 4; mj++) {
                    fma2(acc[mj][nj], wv.x, xf[mj].x);
                    fma2(acc[mj][nj], wv.y, xf[mj].y);
                }
            }
        }
        __syncthreads();
    }

    // epilogue -> g_xg[t][b][n]
#pragma unroll
    for (int mj = 0; mj < 4; mj++) {
        int m = m0 + wm * 32 + mj * 8 + ml;
        int b = m >> 9;              // S_ = 512
        int t = m & (S_ - 1);
        float* dst = g_xg + ((size_t)t * B_ + b) * NG;
#pragma unroll
        for (int nj = 0; nj < 8; nj++) {
            int n = n0 + wn * 32 + nj * 4 + nl;
            dst[n] = unpk_sum(acc[mj][nj]);
        }
    }
}

// ===========================================================================
// Phase 2: persistent sequential scan. 128 CTAs, CTA owns 8 hidden cols.
// Wh slice (4 gates x 8 rows x 1024) resident in SMEM for all 512 steps.
// ===========================================================================
__device__ __forceinline__ void grid_barrier() {
    __syncthreads();
    if (threadIdx.x == 0) {
        __threadfence();                                  // release
        unsigned gen = *(volatile unsigned*)&g_bar_gen;
        if (atomicAdd(&g_bar_count, 1u) == NCTA - 1) {
            atomicExch(&g_bar_count, 0u);
            __threadfence();
            atomicAdd(&g_bar_gen, 1u);
        } else {
            while (*(volatile unsigned*)&g_bar_gen == gen) __nanosleep(64);
        }
        __threadfence();                                  // acquire (invalidates L1)
    }
    __syncthreads();
}

// dynamic smem layout (bytes): Wsm 131072 | hsm 67584 | csm 2048 | bsm 128
#define P2_SMEM 200832

__global__ void __launch_bounds__(256, 1) lstm_seq(
    const float* __restrict__ Wf, const float* __restrict__ bf,
    const float* __restrict__ Wi, const float* __restrict__ bi,
    const float* __restrict__ Wc, const float* __restrict__ bc,
    const float* __restrict__ Wo, const float* __restrict__ bo,
    float* __restrict__ out)
{
    extern __shared__ float smf[];
    float* Wsm  = smf;                        // [32][1024]
    float* hsm  = smf + 32 * 1024;            // [2][64][132] (padded rows)
    float* csm  = hsm + 2 * 64 * 132;         // [64*8] cell state, SMEM-resident
    float* bsm  = csm + 512;                  // [32] biases
    ull*   red  = (ull*)hsm;                  // overlay: [32][64] k-group partials
    float* zbuf = hsm + 4096;                 // overlay: [32][64] gate preacts

    const int tid = threadIdx.x;
    const int cta = blockIdx.x;
    const float* Wp[4] = {Wf, Wi, Wc, Wo};
    const float* bp[4] = {bf, bi, bc, bo};

    // ---- one-time: load Wh slice (h-part = cols [1024,2048) of each W row)
#pragma unroll
    for (int j = 0; j < 32; j++) {
        int f = tid + j * 256;                 // 8192 float4 total
        int nl_ = f >> 8, c4 = f & 255;
        int g = nl_ >> 3, r = nl_ & 7;
        float4 v = *(const float4*)(Wp[g] + (size_t)(cta * 8 + r) * 2048 + 1024 + c4 * 4);
        *(float4*)&Wsm[nl_ * 1024 + c4 * 4] = v;
    }
    if (tid < 32) bsm[tid] = bp[tid >> 3][cta * 8 + (tid & 7)];
    for (int i = tid; i < 512; i += 256) {
        csm[i] = 0.f;
        int b = i >> 3, r = i & 7;
        g_h[0][b * H_ + cta * 8 + r] = 0.f;    // h0 = 0 (this CTA's columns)
    }
    grid_barrier();

    const int lane = tid & 31;
    const int warp = tid >> 5;
    const int kg = warp >> 2;                  // split-K group: k<512 / k>=512
    const int g  = warp & 3;                   // gate handled by this warp
    const int b0 = lane, b1 = lane + 32;
    const int tg = tid & 127;

    for (int t = 0; t < S_; t++) {
        const float* hcur = g_h[t & 1];
        ull acc[8][2];
#pragma unroll
        for (int r = 0; r < 8; r++) { acc[r][0] = 0ull; acc[r][1] = 0ull; }

#pragma unroll 1
        for (int ch = 0; ch < 4; ch++) {
            const int kb = kg * 512 + ch * 128;
            // stage h chunk [64][128] for this k-group (L2 -> SMEM, L1-bypass)
#pragma unroll
            for (int j = 0; j < 16; j++) {
                int f = tg + j * 128;
                int bb = f >> 5, c4 = f & 31;
                float4 v = __ldcg((const float4*)(hcur + bb * H_ + kb + c4 * 4));
                *(float4*)&hsm[(kg * 64 + bb) * 132 + c4 * 4] = v;
            }
            __syncthreads();
            const float* hb = hsm + kg * 64 * 132;
            const float* wb = Wsm + g * 8 * 1024 + kb;
#pragma unroll 8
            for (int kk = 0; kk < 128; kk += 4) {
                ulonglong2 h0 = *(const ulonglong2*)(hb + b0 * 132 + kk);
                ulonglong2 h1 = *(const ulonglong2*)(hb + b1 * 132 + kk);
#pragma unroll
                for (int r = 0; r < 8; r++) {
                    ulonglong2 wv = *(const ulonglong2*)(wb + r * 1024 + kk);
                    fma2(acc[r][0], wv.x, h0.x);
                    fma2(acc[r][0], wv.y, h0.y);
                    fma2(acc[r][1], wv.x, h1.x);
                    fma2(acc[r][1], wv.y, h1.y);
                }
            }
            __syncthreads();
        }

        // ---- reduce split-K groups (hsm region reused as scratch)
        if (kg == 1) {
#pragma unroll
            for (int r = 0; r < 8; r++) {
                red[(g * 8 + r) * 64 + b0] = acc[r][0];
                red[(g * 8 + r) * 64 + b1] = acc[r][1];
            }
        }
        __syncthreads();
        if (kg == 0) {
            const float* xg = g_xg + (size_t)t * B_ * NG + g * 1024 + cta * 8;
#pragma unroll
            for (int r = 0; r < 8; r++) {
                int nl_ = g * 8 + r;
                float z0 = unpk_sum(acc[r][0]) + unpk_sum(red[nl_ * 64 + b0])
                         + bsm[nl_] + __ldg(xg + (size_t)b0 * NG + r);
                float z1 = unpk_sum(acc[r][1]) + unpk_sum(red[nl_ * 64 + b1])
                         + bsm[nl_] + __ldg(xg + (size_t)b1 * NG + r);
                zbuf[nl_ * 64 + b0] = z0;
                zbuf[nl_ * 64 + b1] = z1;
            }
        }
        __syncthreads();

        // ---- elementwise gate math, c stays in SMEM, h -> global + output
        float* hnext = g_h[(t + 1) & 1];
        for (int i = tid; i < 512; i += 256) {
            int b = i >> 3, r = i & 7;
            float zf = zbuf[(0  + r) * 64 + b];
            float zi = zbuf[(8  + r) * 64 + b];
            float zg = zbuf[(16 + r) * 64 + b];
            float zo = zbuf[(24 + r) * 64 + b];
            float fg = sigm(zf);
            float ig = sigm(zi);
            float gg = tanhf(zg);
            float og = sigm(zo);
            float c  = fg * csm[i] + ig * gg;
            csm[i] = c;
            float h = og * tanhf(c);
            int hc = cta * 8 + r;
            hnext[b * H_ + hc] = h;
            out[((size_t)b * S_ + t) * H_ + hc] = h;
            if (t == S_ - 1) {
                out[(size_t)B_ * S_ * H_ + b * H_ + hc] = h;                 // hT
                out[(size_t)B_ * S_ * H_ + (size_t)B_ * H_ + b * H_ + hc] = c; // cT
            }
        }
        grid_barrier();
    }
}

// ===========================================================================
extern "C" void kernel_launch(void* const* d_in, const int* in_sizes, int n_in,
                              void* d_out, int out_size) {
    const float* x  = (const float*)d_in[0];
    const float* Wf = (const float*)d_in[1];
    const float* bf = (const float*)d_in[2];
    const float* Wi = (const float*)d_in[3];
    const float* bi = (const float*)d_in[4];
    const float* Wc = (const float*)d_in[5];
    const float* bc = (const float*)d_in[6];
    const float* Wo = (const float*)d_in[7];
    const float* bo = (const float*)d_in[8];
    float* out = (float*)d_out;

    dim3 g1(NG / P1_TN, (B_ * S_) / P1_TM);   // (64, 256)
    lstm_xgemm<<<g1, 256>>>(x, Wf, Wi, Wc, Wo);

    cudaFuncSetAttribute(lstm_seq, cudaFuncAttributeMaxDynamicSharedMemorySize, P2_SMEM);
    lstm_seq<<<NCTA, 256, P2_SMEM>>>(Wf, bf, Wi, bi, Wc, bc, Wo, bo, out);
}